// round 13
// baseline (speedup 1.0000x reference)
#include <cuda_runtime.h>
#include <cuda_bf16.h>
#include <mma.h>

using namespace nvcuda;

#define EMAX 800000
#define NMAX 100000
#define SLOPE_ 0.1f
#define EPS_ 1e-5f

// ---------------- scratch (device globals; no allocation allowed) ----------------
__device__ float g_hA[(size_t)EMAX * 64];   // edge intermediate A
__device__ float g_hB[(size_t)EMAX * 64];   // edge intermediate B
__device__ float g_agg[(size_t)NMAX * 64];  // scatter-sum result
__device__ float g_h2A[(size_t)NMAX * 96];
__device__ float g_h2B[(size_t)NMAX * 96];
__device__ int   g_deg[NMAX];
__device__ float g_sum[6][96];
__device__ float g_sq[6][96];
__device__ float g_Wf[6][96 * 96];          // folded (scale*W) per stage (fp32, node path)
__device__ float g_cf[6][96];               // folded bias per stage
// bf16-split weights for edge stages 0..2, row-major [k'][j], k' in [0,192):
//   rows [0,64)=Whi, [64,128)=Whi (for A-lo term), [128,192)=Wlo (for A-hi term)
__device__ __align__(16) __nv_bfloat16 g_Wbf[3][192 * 64];

// ================= edge-MLP wmma kernel =================
// SMEM: [0,256) cf; [256, 256+24576) B' bf16 [192][64];
//       [25088, 25088+49152) A' bf16 [128][192]  (reused as fp32 out [128][76])
#define SMW_CF 0
#define SMW_B  256
#define SMW_A  25088
#define SMW_TOTAL (25088 + 49152)
#define OUT_LD 76

template <bool GATHER, bool LRELU, bool STATS, bool SCATTER>
__global__ __launch_bounds__(256) void k_wmma(const float* __restrict__ src,
                                              const float* __restrict__ x,
                                              const int* __restrict__ row,
                                              const int* __restrict__ col,
                                              float* __restrict__ dst,
                                              int rows, int stage, int ostage) {
    extern __shared__ char smem[];
    float* sCF = (float*)(smem + SMW_CF);
    __nv_bfloat16* sB = (__nv_bfloat16*)(smem + SMW_B);
    __nv_bfloat16* sA = (__nv_bfloat16*)(smem + SMW_A);
    float* sOut = (float*)(smem + SMW_A);   // reused after MMA
    int tid = threadIdx.x, wid = tid >> 5;
    int base = blockIdx.x * 128;

    if (tid < 64) sCF[tid] = g_cf[stage][tid];

    // ---- B' staging: 192x64 bf16 = 1536 uint4, 6 per thread ----
    {
        const uint4* gb = (const uint4*)g_Wbf[stage];
        uint4* bb = (uint4*)sB;
#pragma unroll
        for (int i = 0; i < 6; i++) bb[tid + 256 * i] = gb[tid + 256 * i];
    }

    // ---- A' staging: thread handles row tid>>1, half (32 cols) tid&1 ----
    {
        int r = tid >> 1, h = tid & 1;
        int e = base + r;
        float af[32];
        if (e < rows) {
            const float4* p;
            if (GATHER)
                p = (h == 0) ? (const float4*)(x + (size_t)row[e] * 32)
                             : (const float4*)(src + (size_t)e * 32);
            else
                p = (const float4*)(src + (size_t)e * 64 + 32 * h);
#pragma unroll
            for (int i = 0; i < 8; i++) {
                float4 t = p[i];
                af[4 * i] = t.x; af[4 * i + 1] = t.y; af[4 * i + 2] = t.z; af[4 * i + 3] = t.w;
            }
        } else {
#pragma unroll
            for (int i = 0; i < 32; i++) af[i] = 0.f;
        }
        __nv_bfloat162* aHi  = (__nv_bfloat162*)(sA + r * 192 + 32 * h);
        __nv_bfloat162* aLo  = (__nv_bfloat162*)(sA + r * 192 + 64 + 32 * h);
        __nv_bfloat162* aHi2 = (__nv_bfloat162*)(sA + r * 192 + 128 + 32 * h);
#pragma unroll
        for (int i = 0; i < 16; i++) {
            float a0 = af[2 * i], a1 = af[2 * i + 1];
            __nv_bfloat16 h0 = __float2bfloat16_rn(a0);
            __nv_bfloat16 h1 = __float2bfloat16_rn(a1);
            __nv_bfloat162 hp; hp.x = h0; hp.y = h1;
            __nv_bfloat162 lp;
            lp.x = __float2bfloat16_rn(a0 - __bfloat162float(h0));
            lp.y = __float2bfloat16_rn(a1 - __bfloat162float(h1));
            aHi[i] = hp; aLo[i] = lp; aHi2[i] = hp;
        }
    }
    __syncthreads();

    // ---- MMA: warp w computes rows [16w,16w+16) x cols [0,64), K'=192 ----
    wmma::fragment<wmma::accumulator, 16, 16, 16, float> acc[4];
#pragma unroll
    for (int n = 0; n < 4; n++) wmma::fill_fragment(acc[n], 0.f);
#pragma unroll
    for (int ks = 0; ks < 12; ks++) {
        wmma::fragment<wmma::matrix_a, 16, 16, 16, __nv_bfloat16, wmma::row_major> fa;
        wmma::load_matrix_sync(fa, sA + (wid * 16) * 192 + ks * 16, 192);
#pragma unroll
        for (int n = 0; n < 4; n++) {
            wmma::fragment<wmma::matrix_b, 16, 16, 16, __nv_bfloat16, wmma::row_major> fb;
            wmma::load_matrix_sync(fb, sB + (ks * 16) * 64 + n * 16, 64);
            wmma::mma_sync(acc[n], fa, fb, acc[n]);
        }
    }
    __syncthreads();   // all warps done reading sA before reuse as sOut
#pragma unroll
    for (int n = 0; n < 4; n++)
        wmma::store_matrix_sync(sOut + (wid * 16) * OUT_LD + n * 16, acc[n], OUT_LD,
                                wmma::mem_row_major);
    __syncthreads();

    // ---- epilogue: bias + lrelu + (store | scatter) + fused stats ----
    int r = tid >> 1, h = tid & 1;
    int e = base + r;
    bool v = e < rows;
    float out[32];
    float* po = sOut + r * OUT_LD + 32 * h;
#pragma unroll
    for (int i = 0; i < 32; i++) {
        float o = po[i] + sCF[32 * h + i];
        if (LRELU) o = o > 0.f ? o : SLOPE_ * o;
        out[i] = o;
    }
    if (v) {
        if (SCATTER) {
            float* dp = g_agg + (size_t)col[e] * 64 + 32 * h;
#pragma unroll
            for (int i = 0; i < 32; i += 4) {
                asm volatile("red.global.add.v4.f32 [%0], {%1, %2, %3, %4};"
                             :: "l"(dp + i), "f"(out[i]), "f"(out[i + 1]),
                                "f"(out[i + 2]), "f"(out[i + 3]) : "memory");
            }
        } else {
            float4* dp = (float4*)(dst + (size_t)e * 64 + 32 * h);
#pragma unroll
            for (int i = 0; i < 8; i++)
                dp[i] = make_float4(out[4 * i], out[4 * i + 1], out[4 * i + 2], out[4 * i + 3]);
        }
    }
    if (STATS) {
#pragma unroll
        for (int i = 0; i < 32; i++) po[i] = v ? out[i] : 0.f;
        __syncthreads();
        int c = tid & 63, q = tid >> 6;     // 4 quarters x 64 cols
        float s = 0.f, sq = 0.f;
        for (int rr = q * 32; rr < q * 32 + 32; rr++) {
            float val = sOut[rr * OUT_LD + c];
            s += val; sq += val * val;
        }
        atomicAdd(&g_sum[ostage][c], s);
        atomicAdd(&g_sq[ostage][c], sq);
    }
}

// ================= scalar path (R0-proven) for node MLP + stats =================
__global__ void k_zero(int n, int nagg) {
    int stride = gridDim.x * blockDim.x;
    int i0 = blockIdx.x * blockDim.x + threadIdx.x;
    for (int i = i0; i < nagg; i += stride) g_agg[i] = 0.f;
    for (int i = i0; i < n; i += stride) g_deg[i] = 0;
    if (i0 < 6 * 96) { (&g_sum[0][0])[i0] = 0.f; (&g_sq[0][0])[i0] = 0.f; }
}

__global__ void k_deg(const int* __restrict__ row, int E) {
    int e = blockIdx.x * blockDim.x + threadIdx.x;
    if (e < E) atomicAdd(&g_deg[row[e]], 1);
}

__global__ void k_degw(const float* __restrict__ x, int n) {
    int c = threadIdx.x & 31;
    int g = threadIdx.x >> 5;
    int gpb = blockDim.x >> 5;
    float s = 0.f, q = 0.f;
    for (int r = blockIdx.x * gpb + g; r < n; r += gridDim.x * gpb) {
        float w = (float)g_deg[r];
        float v = x[(size_t)r * 32 + c];
        float wv = w * v;
        s += wv; q += wv * v;
    }
    atomicAdd(&g_sum[0][c], s);
    atomicAdd(&g_sq[0][c], q);
}

template <int C>
__global__ void k_colstats(const float* __restrict__ src, int rows, int stage, int coff) {
    int gpb = blockDim.x / C;
    int c = threadIdx.x % C;
    int g = threadIdx.x / C;
    if (g >= gpb) return;
    float s = 0.f, q = 0.f;
    for (int r = blockIdx.x * gpb + g; r < rows; r += gridDim.x * gpb) {
        float v = src[(size_t)r * C + c];
        s += v; q += v * v;
    }
    atomicAdd(&g_sum[stage][coff + c], s);
    atomicAdd(&g_sq[stage][coff + c], q);
}

// fold BN stats into weights; for stages 0..2 also emit bf16-split [k'][j] weights
__global__ void k_prep(int stage, float invR,
                       const float* __restrict__ gg, const float* __restrict__ bb,
                       const float* __restrict__ W, const float* __restrict__ c,
                       int IN, int OUT) {
    __shared__ float sSc[96], sSh[96];
    int t = threadIdx.x;
    if (t < IN) {
        float m = g_sum[stage][t] * invR;
        float var = g_sq[stage][t] * invR - m * m;
        float sc = gg[t] * rsqrtf(var + EPS_);
        sSc[t] = sc;
        sSh[t] = bb[t] - m * sc;
    }
    __syncthreads();
    for (int j = t; j < OUT; j += blockDim.x) {
        float a = c[j];
        for (int k = 0; k < IN; k++) {
            float w = W[k * OUT + j];
            float wf = sSc[k] * w;
            g_Wf[stage][k * OUT + j] = wf;
            if (stage < 3) {
                __nv_bfloat16 hi = __float2bfloat16_rn(wf);
                g_Wbf[stage][k * 64 + j] = hi;                 // rows [0,64): Whi
                g_Wbf[stage][(64 + k) * 64 + j] = hi;          // rows [64,128): Whi (A-lo term)
                g_Wbf[stage][(128 + k) * 64 + j] =
                    __float2bfloat16_rn(wf - __bfloat162float(hi));  // rows [128,192): Wlo
            }
            a += sSh[k] * w;
        }
        g_cf[stage][j] = a;
    }
}

template <int W>
__device__ __forceinline__ void stage_copy(const float* __restrict__ src, int base, int rows,
                                           float* sIn, int stride, int coff) {
    const int total = 128 * (W / 4);
    for (int idx = threadIdx.x; idx < total; idx += blockDim.x) {
        int r = idx / (W / 4);
        int kk = (idx % (W / 4)) * 4;
        if (base + r < rows) {
            float4 v = *(const float4*)(src + (size_t)(base + r) * W + kk);
            float* d = sIn + r * stride + coff + kk;
            d[0] = v.x; d[1] = v.y; d[2] = v.z; d[3] = v.w;
        }
    }
}

template <int IN, int OUT, bool LRELU>
__device__ __forceinline__ void gemm_one(const float* __restrict__ sIn, const float* __restrict__ sW,
                                         const float* __restrict__ cf, float* acc) {
#pragma unroll
    for (int j = 0; j < OUT; j++) acc[j] = __ldg(cf + j);
#pragma unroll 4
    for (int k = 0; k < IN; k++) {
        float v = sIn[k];
#pragma unroll
        for (int j = 0; j < OUT; j++) acc[j] = fmaf(v, sW[k * OUT + j], acc[j]);
    }
    if (LRELU) {
#pragma unroll
        for (int j = 0; j < OUT; j++) acc[j] = acc[j] > 0.f ? acc[j] : SLOPE_ * acc[j];
    }
}

template <int IN, int OUT, bool LRELU>
__global__ __launch_bounds__(128) void k_layer(const float* __restrict__ src, float* __restrict__ dst,
                                               int rows, int stage) {
    extern __shared__ float sm[];
    float* sW = sm;
    float* sIn = sm + IN * OUT;
    for (int i = threadIdx.x; i < IN * OUT / 4; i += 128)
        ((float4*)sW)[i] = ((const float4*)g_Wf[stage])[i];
    int base = blockIdx.x * 128;
    stage_copy<IN>(src, base, rows, sIn, IN + 1, 0);
    __syncthreads();
    int r = base + threadIdx.x;
    if (r >= rows) return;
    float acc[OUT];
    gemm_one<IN, OUT, LRELU>(sIn + threadIdx.x * (IN + 1), sW, g_cf[stage], acc);
    float* d = dst + (size_t)r * OUT;
#pragma unroll
    for (int j = 0; j < OUT; j += 4)
        *(float4*)(d + j) = make_float4(acc[j], acc[j + 1], acc[j + 2], acc[j + 3]);
}

__global__ __launch_bounds__(128) void k_node1(const float* __restrict__ x, float* __restrict__ dst,
                                               int n, int stage) {
    extern __shared__ float sm[];
    float* sW = sm;
    float* sIn = sm + 96 * 96;
    for (int i = threadIdx.x; i < 96 * 96 / 4; i += 128)
        ((float4*)sW)[i] = ((const float4*)g_Wf[stage])[i];
    int base = blockIdx.x * 128;
    stage_copy<32>(x, base, n, sIn, 97, 0);
    stage_copy<64>(g_agg, base, n, sIn, 97, 32);
    __syncthreads();
    int r = base + threadIdx.x;
    if (r >= n) return;
    float acc[96];
    gemm_one<96, 96, true>(sIn + threadIdx.x * 97, sW, g_cf[stage], acc);
    float* d = dst + (size_t)r * 96;
#pragma unroll
    for (int j = 0; j < 96; j += 4)
        *(float4*)(d + j) = make_float4(acc[j], acc[j + 1], acc[j + 2], acc[j + 3]);
}

// ---------------- launcher ----------------
extern "C" void kernel_launch(void* const* d_in, const int* in_sizes, int n_in,
                              void* d_out, int out_size) {
    (void)n_in; (void)out_size;
    const float* x  = (const float*)d_in[0];
    const int*   ei = (const int*)d_in[1];
    const float* ea = (const float*)d_in[2];
    const float* m1g1 = (const float*)d_in[5],  *m1b1 = (const float*)d_in[6];
    const float* m1w1 = (const float*)d_in[7],  *m1c1 = (const float*)d_in[8];
    const float* m1g2 = (const float*)d_in[9],  *m1b2 = (const float*)d_in[10];
    const float* m1w2 = (const float*)d_in[11], *m1c2 = (const float*)d_in[12];
    const float* m1g3 = (const float*)d_in[13], *m1b3 = (const float*)d_in[14];
    const float* m1w3 = (const float*)d_in[15], *m1c3 = (const float*)d_in[16];
    const float* m2g1 = (const float*)d_in[17], *m2b1 = (const float*)d_in[18];
    const float* m2w1 = (const float*)d_in[19], *m2c1 = (const float*)d_in[20];
    const float* m2g2 = (const float*)d_in[21], *m2b2 = (const float*)d_in[22];
    const float* m2w2 = (const float*)d_in[23], *m2c2 = (const float*)d_in[24];
    const float* m2g3 = (const float*)d_in[25], *m2b3 = (const float*)d_in[26];
    const float* m2w3 = (const float*)d_in[27], *m2c3 = (const float*)d_in[28];

    int N = in_sizes[0] / 32;
    int E = in_sizes[2] / 32;
    const int* rowp = ei;
    const int* colp = ei + E;

    float *hA, *hB, *aggp, *h2A, *h2B;
    cudaGetSymbolAddress((void**)&hA, g_hA);
    cudaGetSymbolAddress((void**)&hB, g_hB);
    cudaGetSymbolAddress((void**)&aggp, g_agg);
    cudaGetSymbolAddress((void**)&h2A, g_h2A);
    cudaGetSymbolAddress((void**)&h2B, g_h2B);

    const int SM96    = (96 * 96 + 128 * 97) * 4;
    const int SM96_32 = (96 * 32 + 128 * 97) * 4;
    cudaFuncSetAttribute(k_wmma<true, true, true, false>, cudaFuncAttributeMaxDynamicSharedMemorySize, SMW_TOTAL);
    cudaFuncSetAttribute(k_wmma<false, true, true, false>, cudaFuncAttributeMaxDynamicSharedMemorySize, SMW_TOTAL);
    cudaFuncSetAttribute(k_wmma<false, false, false, true>, cudaFuncAttributeMaxDynamicSharedMemorySize, SMW_TOTAL);
    cudaFuncSetAttribute(k_node1, cudaFuncAttributeMaxDynamicSharedMemorySize, SM96);
    cudaFuncSetAttribute(k_layer<96, 96, true>, cudaFuncAttributeMaxDynamicSharedMemorySize, SM96);
    cudaFuncSetAttribute(k_layer<96, 32, false>, cudaFuncAttributeMaxDynamicSharedMemorySize, SM96_32);

    int ebl = (E + 127) / 128;
    int nbl = (N + 127) / 128;

    k_zero<<<2048, 256>>>(N, N * 64);
    // stats of h0 = [x[row] | edge_attr] (degree trick for the x half)
    k_colstats<32><<<512, 256>>>(ea, E, 0, 32);
    k_deg<<<(E + 255) / 256, 256>>>(rowp, E);
    k_degw<<<1024, 256>>>(x, N);
    k_prep<<<1, 128>>>(0, 1.0f / E, m1g1, m1b1, m1w1, m1c1, 64, 64);
    // edge layer 1: gather + GEMM + lrelu + fused stats(hA)
    k_wmma<true, true, true, false><<<ebl, 256, SMW_TOTAL>>>(ea, x, rowp, nullptr, hA, E, 0, 1);

    k_prep<<<1, 128>>>(1, 1.0f / E, m1g2, m1b2, m1w2, m1c2, 64, 64);
    // edge layer 2 + fused stats(hB)
    k_wmma<false, true, true, false><<<ebl, 256, SMW_TOTAL>>>(hA, nullptr, nullptr, nullptr, hB, E, 1, 2);

    k_prep<<<1, 128>>>(2, 1.0f / E, m1g3, m1b3, m1w3, m1c3, 64, 64);
    // edge layer 3 + scatter-sum
    k_wmma<false, false, false, true><<<ebl, 256, SMW_TOTAL>>>(hB, nullptr, nullptr, colp, nullptr, E, 2, 0);

    // stats of h2 = [x | agg]
    k_colstats<32><<<256, 256>>>(x, N, 3, 0);
    k_colstats<64><<<256, 256>>>(aggp, N, 3, 32);
    k_prep<<<1, 128>>>(3, 1.0f / N, m2g1, m2b1, m2w1, m2c1, 96, 96);
    k_node1<<<nbl, 128, SM96>>>(x, h2A, N, 3);

    k_colstats<96><<<256, 288>>>(h2A, N, 4, 0);
    k_prep<<<1, 128>>>(4, 1.0f / N, m2g2, m2b2, m2w2, m2c2, 96, 96);
    k_layer<96, 96, true><<<nbl, 128, SM96>>>(h2A, h2B, N, 4);

    k_colstats<96><<<256, 288>>>(h2B, N, 5, 0);
    k_prep<<<1, 128>>>(5, 1.0f / N, m2g3, m2b3, m2w3, m2c3, 96, 32);
    k_layer<96, 32, false><<<nbl, 128, SM96_32>>>(h2B, (float*)d_out, N, 5);
}